// round 11
// baseline (speedup 1.0000x reference)
#include <cuda_runtime.h>

// crossMSEloss: B=4, S=256, P=64, D=63
// out[b,s] = sum_p conf[p] * min_q ||pred_p - tgt_q||
//          + sum_q min_p ( ||pred_p - tgt_q|| / conf[p] )
//
// GEMM-form (norm trick). 64-thread blocks, one (b,s) pair each, 8x8 register
// tiles (1 B of smem traffic per MAC vs 2 B at 4x4 -- the kernel is smem-
// crossbar bound at 128B/cyc/SM). f32x2 FMAs packed along q. Transposed
// targets with chunk swizzle key (d>>2)&7: constant within a 4-d chunk
// (hoistable, conflict-free reads), per-lane-varying in the scatter.

#define SP_S 68

typedef unsigned long long u64;

__device__ __forceinline__ u64 pack2(float x) {
    u64 r; asm("mov.b64 %0, {%1, %1};" : "=l"(r) : "f"(x)); return r;
}
__device__ __forceinline__ void ffma2(u64& d, u64 a, u64 b) {
    asm("fma.rn.f32x2 %0, %1, %2, %0;" : "+l"(d) : "l"(a), "l"(b));
}
__device__ __forceinline__ void unpack2(float& lo, float& hi, u64 v) {
    asm("mov.b64 {%0, %1}, %2;" : "=f"(lo), "=f"(hi) : "l"(v));
}

// st_t physical float offset: row d (64 floats), chunk (q>>2)^((d>>2)&7), +(q&3)
__device__ __forceinline__ int stoff(int d, int q) {
    return d * 64 + (((q >> 2) ^ ((d >> 2) & 7)) << 2) + (q & 3);
}

__global__ __launch_bounds__(64, 6)
void cross_mse_loss_kernel(const float* __restrict__ inp,
                           const float* __restrict__ tgt,
                           float* __restrict__ out)
{
    __shared__ __align__(16) float sp[64 * SP_S];   // preds [p][d], d63 -> 0
    __shared__ __align__(16) float st_t[64 * 64];   // targets [d][swizzled q]
    __shared__ float cm[2 * 68];                    // per-warp col-min partials
    __shared__ float rm[64];
    __shared__ float conf[64];
    __shared__ float ci2s[64];
    __shared__ float pn[64];
    __shared__ float qn[64];
    __shared__ float red[2];

    const int bs  = blockIdx.x;
    const int tid = threadIdx.x;          // 64 threads
    const int tx  = tid & 7;              // q-octet
    const int ty  = tid >> 3;             // p-octet
    const int lane = tid & 31;
    const int w    = tid >> 5;

    const float* ip = inp + (size_t)bs * 4096;
    const float* tp = tgt + (size_t)bs * 4032;

    // ================= Front end: batched loads (single exposure) ========
    const float4* ip4 = (const float4*)ip;   // 1024
    const float4* tp4 = (const float4*)tp;   // 1008

    float4 pv[16];
    #pragma unroll
    for (int r = 0; r < 16; r++) pv[r] = ip4[tid + r * 64];
    float4 tv[16];
    #pragma unroll
    for (int r = 0; r < 16; r++) {
        int idx = tid + r * 64;
        tv[r] = (idx < 1008) ? tp4[idx] : make_float4(0.f, 0.f, 0.f, 0.f);
    }

    // zero pad row d=63 of st_t (scatter never writes d=63)
    st_t[63 * 64 + tid] = 0.0f;

    // preds -> sp (STS.128); conf on the d4==60 lane
    #pragma unroll
    for (int r = 0; r < 16; r++) {
        int idx = tid + r * 64;
        int p   = idx >> 4;
        int d4  = (idx & 15) << 2;
        float4 v = pv[r];
        if (d4 == 60) {
            conf[p] = v.w;
            float ci = 1.0f / v.w;
            ci2s[p] = ci * ci;
            v.w = 0.0f;
        }
        *(float4*)(sp + p * SP_S + d4) = v;
    }

    // targets -> swizzled st_t (per-component scatter)
    #pragma unroll
    for (int r = 0; r < 16; r++) {
        int idx = tid + r * 64;
        if (idx < 1008) {
            int e0 = idx << 2;
            float vv[4] = {tv[r].x, tv[r].y, tv[r].z, tv[r].w};
            #pragma unroll
            for (int c = 0; c < 4; c++) {
                int e = e0 + c;
                int q = e / 63;
                int d = e - q * 63;
                st_t[stoff(d, q)] = vv[c];
            }
        }
    }
    __syncthreads();

    // ================= Norms phase =================
    {
        // pn[t]: conflict-light float4 scan of pred row t
        const float4* ap = (const float4*)(sp + tid * SP_S);
        float s = 0.0f;
        #pragma unroll
        for (int k = 0; k < 16; k++) {
            float4 a = ap[k];
            s = fmaf(a.x, a.x, fmaf(a.y, a.y, fmaf(a.z, a.z, fmaf(a.w, a.w, s))));
        }
        pn[tid] = s;
        // qn[t]: scan swizzled column t (conflict-free: 32 distinct banks/round)
        float s2 = 0.0f;
        #pragma unroll
        for (int dg = 0; dg < 16; dg++) {
            const int chunk = ((tid >> 2) ^ (dg & 7)) << 2;
            const float* base = st_t + dg * 256 + chunk + (tid & 3);
            s2 = fmaf(base[0],   base[0],   s2);
            s2 = fmaf(base[64],  base[64],  s2);
            s2 = fmaf(base[128], base[128], s2);
            s2 = fmaf(base[192], base[192], s2);
        }
        qn[tid] = s2;
    }
    __syncthreads();

    // ================= Mainloop: 8p x 8q, f32x2 along q =================
    const int q0 = tx * 8;
    const int p0 = ty * 8;

    u64 acc[8][4];
    #pragma unroll
    for (int i = 0; i < 8; i++)
        #pragma unroll
        for (int j = 0; j < 4; j++) acc[i][j] = 0ull;

    const float* a0 = sp + p0 * SP_S;

    #pragma unroll
    for (int dc = 0; dc < 64; dc += 4) {
        const int key = (dc >> 2) & 7;
        const int c0 = ((2 * tx) ^ key) << 2;
        const int c1 = ((2 * tx + 1) ^ key) << 2;
        ulonglong2 b0[4], b1[4];
        #pragma unroll
        for (int d = 0; d < 4; d++) {
            b0[d] = *(const ulonglong2*)(st_t + (dc + d) * 64 + c0);
            b1[d] = *(const ulonglong2*)(st_t + (dc + d) * 64 + c1);
        }
        #pragma unroll
        for (int i = 0; i < 8; i++) {
            float4 av = *(const float4*)(a0 + i * SP_S + dc);
            float a[4] = {av.x, av.y, av.z, av.w};
            #pragma unroll
            for (int d = 0; d < 4; d++) {
                u64 pa = pack2(a[d]);
                ffma2(acc[i][0], pa, b0[d].x);
                ffma2(acc[i][1], pa, b0[d].y);
                ffma2(acc[i][2], pa, b1[d].x);
                ffma2(acc[i][3], pa, b1[d].y);
            }
        }
    }

    // ================= Epilogue =================
    float pnr[8], ci2[8], qnr[8];
    #pragma unroll
    for (int i = 0; i < 8; i++) { pnr[i] = pn[p0 + i]; ci2[i] = ci2s[p0 + i]; }
    #pragma unroll
    for (int j = 0; j < 8; j++) qnr[j] = qn[q0 + j];

    float cmin[8];
    #pragma unroll
    for (int j = 0; j < 8; j++) cmin[j] = 1e30f;
    float rmin[8];

    #pragma unroll
    for (int i = 0; i < 8; i++) {
        float dot[8];
        unpack2(dot[0], dot[1], acc[i][0]);
        unpack2(dot[2], dot[3], acc[i][1]);
        unpack2(dot[4], dot[5], acc[i][2]);
        unpack2(dot[6], dot[7], acc[i][3]);
        float rmn = 1e30f;
        #pragma unroll
        for (int j = 0; j < 8; j++) {
            float d2 = fmaxf(fmaf(-2.0f, dot[j], pnr[i] + qnr[j]), 0.0f);
            rmn = fminf(rmn, d2);
            cmin[j] = fminf(cmin[j], d2 * ci2[i]);
        }
        rmin[i] = rmn;
    }

    // row mins: reduce over tx (lane bits 0..2)
    #pragma unroll
    for (int m = 1; m < 8; m <<= 1) {
        #pragma unroll
        for (int i = 0; i < 8; i++)
            rmin[i] = fminf(rmin[i], __shfl_xor_sync(0xFFFFFFFFu, rmin[i], m));
    }
    if (tx == 0) {
        #pragma unroll
        for (int i = 0; i < 8; i++) rm[p0 + i] = rmin[i];
    }
    // col mins: reduce over ty within warp (lane bits 3,4), then smem across warps
    #pragma unroll
    for (int j = 0; j < 8; j++) {
        cmin[j] = fminf(cmin[j], __shfl_xor_sync(0xFFFFFFFFu, cmin[j], 8));
        cmin[j] = fminf(cmin[j], __shfl_xor_sync(0xFFFFFFFFu, cmin[j], 16));
    }
    if (lane < 8) {
        #pragma unroll
        for (int j = 0; j < 8; j++) cm[w * 68 + lane * 8 + j] = cmin[j];
    }
    __syncthreads();

    // ================= Final: 128 sqrts + block sum =================
    float val = conf[tid] * sqrtf(rm[tid])
              + sqrtf(fminf(cm[tid], cm[68 + tid]));
    #pragma unroll
    for (int off = 16; off > 0; off >>= 1)
        val += __shfl_xor_sync(0xFFFFFFFFu, val, off);
    if (lane == 0) red[w] = val;
    __syncthreads();
    if (tid == 0) out[bs] = red[0] + red[1];
}

extern "C" void kernel_launch(void* const* d_in, const int* in_sizes, int n_in,
                              void* d_out, int out_size)
{
    const float* inp = (const float*)d_in[0];
    const float* tgt = (const float*)d_in[1];
    float* out = (float*)d_out;
    cross_mse_loss_kernel<<<1024, 64>>>(inp, tgt, out);
}

// round 12
// speedup vs baseline: 1.3053x; 1.3053x over previous
#include <cuda_runtime.h>

// crossMSEloss: B=4, S=256, P=64, D=63
// out[b,s] = sum_p conf[p] * min_q ||pred_p - tgt_q||
//          + sum_q min_p ( ||pred_p - tgt_q|| / conf[p] )
//
// GEMM-form (norm trick) with the 64x64x64 dot matrix on TENSOR CORES:
// split-tf32 mma.sync.m16n8k8 (x = hi + lo; dot = hihi + hilo + lohi,
// error ~2^-22 -- well under the 1e-3 gate). One bs pair per 256-thread
// block; warp w owns D rows 16*(w&3)..+15, cols 32*(w>>2)..+31.
// A ([p][d]) and B ([q][d]) both natural row-major, stride 68
// (fragment loads are 32-lane bank-conflict-free: bank = 4*(lane/4)+lane%4).

#define SP_S 68

__device__ __forceinline__ unsigned tf32_of(float x) {
    unsigned r; asm("cvt.rna.tf32.f32 %0, %1;" : "=r"(r) : "f"(x)); return r;
}
__device__ __forceinline__ void split_tf32(float x, unsigned& hi, unsigned& lo) {
    hi = tf32_of(x);
    lo = tf32_of(x - __uint_as_float(hi));
}
__device__ __forceinline__ void mma_tf32(float c[4], const unsigned a[4],
                                         unsigned b0, unsigned b1) {
    asm("mma.sync.aligned.m16n8k8.row.col.f32.tf32.tf32.f32 "
        "{%0,%1,%2,%3}, {%4,%5,%6,%7}, {%8,%9}, {%0,%1,%2,%3};"
        : "+f"(c[0]), "+f"(c[1]), "+f"(c[2]), "+f"(c[3])
        : "r"(a[0]), "r"(a[1]), "r"(a[2]), "r"(a[3]), "r"(b0), "r"(b1));
}

__global__ __launch_bounds__(256, 4)
void cross_mse_loss_kernel(const float* __restrict__ inp,
                           const float* __restrict__ tgt,
                           float* __restrict__ out)
{
    __shared__ __align__(16) float sp[64 * SP_S];   // preds [p][d], d63 -> 0
    __shared__ __align__(16) float tq[64 * SP_S];   // targets [q][d], d63 -> 0
    __shared__ float pn[64], qn[64], conf[64], ci2s[64];
    __shared__ float rm2[2 * 64];    // per-col-half row mins (d^2)
    __shared__ float cm2[4 * 64];    // per-m-stripe col mins (d^2 * ci2)
    __shared__ float red[128];

    const int bs   = blockIdx.x;
    const int tid  = threadIdx.x;
    const int lane = tid & 31;
    const int w    = tid >> 5;
    const int g    = lane >> 2;      // fragment group (row within tile)
    const int i4   = lane & 3;       // thread-in-group (col/k within tile)
    const int mi   = w & 3;          // m-stripe: rows 16*mi .. +15
    const int ch   = w >> 2;         // col half: cols 32*ch .. +31

    const float* ip = inp + (size_t)bs * 4096;
    const float* tp = tgt + (size_t)bs * 4032;

    // ================= Front end: batched gmem loads =================
    const float4* ip4 = (const float4*)ip;   // 1024
    const float4* tp4 = (const float4*)tp;   // 1008

    float4 pv[4];
    #pragma unroll
    for (int r = 0; r < 4; r++) pv[r] = ip4[tid + r * 256];
    float4 tv[4];
    #pragma unroll
    for (int r = 0; r < 4; r++) {
        int idx = tid + r * 256;
        tv[r] = (idx < 1008) ? tp4[idx] : make_float4(0.f, 0.f, 0.f, 0.f);
    }

    if (tid < 64) tq[tid * SP_S + 63] = 0.0f;   // d=63 pad

    // preds -> sp (STS.128); conf on d4==60 lane
    #pragma unroll
    for (int r = 0; r < 4; r++) {
        int idx = tid + r * 256;
        int p   = idx >> 4;
        int d4  = (idx & 15) << 2;
        float4 v = pv[r];
        if (d4 == 60) {
            conf[p] = v.w;
            float ci = 1.0f / v.w;
            ci2s[p] = ci * ci;
            v.w = 0.0f;
        }
        *(float4*)(sp + p * SP_S + d4) = v;
    }
    // targets -> tq[q][d] (per-component scatter across the 63-row seam)
    #pragma unroll
    for (int r = 0; r < 4; r++) {
        int idx = tid + r * 256;
        if (idx < 1008) {
            int e0 = idx << 2;
            float vv[4] = {tv[r].x, tv[r].y, tv[r].z, tv[r].w};
            #pragma unroll
            for (int c = 0; c < 4; c++) {
                int e = e0 + c;
                int q = e / 63;
                int d = e - q * 63;
                tq[q * SP_S + d] = vv[c];
            }
        }
    }
    __syncthreads();

    // ================= Norms =================
    if (tid < 64) {
        const float4* ap = (const float4*)(sp + tid * SP_S);
        float s = 0.0f;
        #pragma unroll
        for (int k = 0; k < 16; k++) {
            float4 a = ap[k];
            s = fmaf(a.x, a.x, fmaf(a.y, a.y, fmaf(a.z, a.z, fmaf(a.w, a.w, s))));
        }
        pn[tid] = s;
    } else if (tid < 128) {
        const float4* bp = (const float4*)(tq + (tid - 64) * SP_S);
        float s = 0.0f;
        #pragma unroll
        for (int k = 0; k < 16; k++) {
            float4 b = bp[k];
            s = fmaf(b.x, b.x, fmaf(b.y, b.y, fmaf(b.z, b.z, fmaf(b.w, b.w, s))));
        }
        qn[tid - 64] = s;
    }
    __syncthreads();

    // ============ Tensor-core mainloop: split-tf32, 3 products ============
    float c[4][4];
    #pragma unroll
    for (int j = 0; j < 4; j++)
        #pragma unroll
        for (int e = 0; e < 4; e++) c[j][e] = 0.0f;

    const float* arow = sp + (mi * 16 + g) * SP_S;   // rows r1, r1+8 (+8*SP_S)
    const float* brow = tq + (ch * 32 + g) * SP_S;   // n-tiles at +j*8*SP_S

    #pragma unroll
    for (int ks = 0; ks < 8; ks++) {
        const int k0 = ks * 8;
        // A fragment (PTX m16n8k8: a0=(g,i4) a1=(g+8,i4) a2=(g,i4+4) a3=(g+8,i4+4))
        float af0 = arow[k0 + i4];
        float af1 = arow[8 * SP_S + k0 + i4];
        float af2 = arow[k0 + i4 + 4];
        float af3 = arow[8 * SP_S + k0 + i4 + 4];
        unsigned ahi[4], alo[4];
        split_tf32(af0, ahi[0], alo[0]);
        split_tf32(af1, ahi[1], alo[1]);
        split_tf32(af2, ahi[2], alo[2]);
        split_tf32(af3, ahi[3], alo[3]);
        #pragma unroll
        for (int j = 0; j < 4; j++) {
            // B fragment: b0=(k=i4, n=g), b1=(k=i4+4, n=g); n-major rows of tq
            float bf0 = brow[j * 8 * SP_S + k0 + i4];
            float bf1 = brow[j * 8 * SP_S + k0 + i4 + 4];
            unsigned bh0, bl0, bh1, bl1;
            split_tf32(bf0, bh0, bl0);
            split_tf32(bf1, bh1, bl1);
            mma_tf32(c[j], ahi, bh0, bh1);   // hi*hi
            mma_tf32(c[j], ahi, bl0, bl1);   // hi*lo
            mma_tf32(c[j], alo, bh0, bh1);   // lo*hi
        }
    }

    // ================= Epilogue: d^2 + mins =================
    const int r1 = mi * 16 + g;
    const int r2 = r1 + 8;
    const float pn1 = pn[r1], pn2 = pn[r2];
    const float ci1 = ci2s[r1], ci2v = ci2s[r2];

    float rmin1 = 1e30f, rmin2 = 1e30f;
    float cmin[8];
    #pragma unroll
    for (int j = 0; j < 4; j++) {
        const int cb = ch * 32 + j * 8 + 2 * i4;
        const float qn0 = qn[cb], qn1 = qn[cb + 1];
        float d11 = fmaxf(fmaf(-2.0f, c[j][0], pn1 + qn0), 0.0f);
        float d12 = fmaxf(fmaf(-2.0f, c[j][1], pn1 + qn1), 0.0f);
        float d21 = fmaxf(fmaf(-2.0f, c[j][2], pn2 + qn0), 0.0f);
        float d22 = fmaxf(fmaf(-2.0f, c[j][3], pn2 + qn1), 0.0f);
        rmin1 = fminf(rmin1, fminf(d11, d12));
        rmin2 = fminf(rmin2, fminf(d21, d22));
        cmin[2 * j]     = fminf(d11 * ci1, d21 * ci2v);
        cmin[2 * j + 1] = fminf(d12 * ci1, d22 * ci2v);
    }

    // row mins: reduce over i4 (lane bits 0,1)
    rmin1 = fminf(rmin1, __shfl_xor_sync(0xFFFFFFFFu, rmin1, 1));
    rmin1 = fminf(rmin1, __shfl_xor_sync(0xFFFFFFFFu, rmin1, 2));
    rmin2 = fminf(rmin2, __shfl_xor_sync(0xFFFFFFFFu, rmin2, 1));
    rmin2 = fminf(rmin2, __shfl_xor_sync(0xFFFFFFFFu, rmin2, 2));
    if (i4 == 0) {
        rm2[ch * 64 + r1] = rmin1;
        rm2[ch * 64 + r2] = rmin2;
    }
    // col mins: reduce over g (lane bits 2,3,4)
    #pragma unroll
    for (int u = 0; u < 8; u++) {
        cmin[u] = fminf(cmin[u], __shfl_xor_sync(0xFFFFFFFFu, cmin[u], 4));
        cmin[u] = fminf(cmin[u], __shfl_xor_sync(0xFFFFFFFFu, cmin[u], 8));
        cmin[u] = fminf(cmin[u], __shfl_xor_sync(0xFFFFFFFFu, cmin[u], 16));
    }
    if (g == 0) {
        #pragma unroll
        for (int j = 0; j < 4; j++) {
            cm2[mi * 64 + ch * 32 + j * 8 + 2 * i4]     = cmin[2 * j];
            cm2[mi * 64 + ch * 32 + j * 8 + 2 * i4 + 1] = cmin[2 * j + 1];
        }
    }
    __syncthreads();

    // ================= Final: 128 sqrts + block sum =================
    float val = 0.0f;
    if (tid < 64) {
        val = conf[tid] * sqrtf(fminf(rm2[tid], rm2[64 + tid]));
    } else if (tid < 128) {
        int q = tid - 64;
        float m = fminf(fminf(cm2[q], cm2[64 + q]),
                        fminf(cm2[128 + q], cm2[192 + q]));
        val = sqrtf(m);
    }

    if (tid < 128) red[tid] = val;
    __syncthreads();
    if (tid < 64) red[tid] += red[tid + 64];
    __syncthreads();
    if (tid < 32) {
        float s = red[tid] + red[tid + 32];
        #pragma unroll
        for (int off = 16; off > 0; off >>= 1)
            s += __shfl_down_sync(0xFFFFFFFFu, s, off);
        if (tid == 0) out[bs] = s;
    }
}

extern "C" void kernel_launch(void* const* d_in, const int* in_sizes, int n_in,
                              void* d_out, int out_size)
{
    const float* inp = (const float*)d_in[0];
    const float* tgt = (const float*)d_in[1];
    float* out = (float*)d_out;
    cross_mse_loss_kernel<<<1024, 256>>>(inp, tgt, out);
}